// round 1
// baseline (speedup 1.0000x reference)
#include <cuda_runtime.h>
#include <cuda_bf16.h>
#include <math.h>

#define S_LEN 2048
#define DIM 2560
#define N_HEAD 32
#define HEAD_DIM 80
#define ROT_DIM 32
#define INTER 10240
#define EPS 1e-5f

// ---------------- scratch (static device globals; no allocs allowed) ----------------
__device__ float g_h   [S_LEN * DIM];          // post-LN activations
__device__ float g_qkv [S_LEN * 3 * DIM];      // qkv projection
__device__ float g_q   [N_HEAD * S_LEN * HEAD_DIM];
__device__ float g_k   [N_HEAD * S_LEN * HEAD_DIM];
__device__ float g_v   [N_HEAD * S_LEN * HEAD_DIM];
__device__ float g_y   [S_LEN * DIM];          // attention output (pre-WO)
__device__ float g_attn[S_LEN * DIM];          // WO output
__device__ float g_ffn1[S_LEN * INTER];        // gelu(h @ w1^T + b1)

// ---------------- LayerNorm ----------------
__global__ void ln_kernel(const float* __restrict__ x,
                          const float* __restrict__ w,
                          const float* __restrict__ b,
                          float* __restrict__ out)
{
    const int s = blockIdx.x;
    const int tid = threadIdx.x;
    const float* row = x + (size_t)s * DIM;
    float sum = 0.f, sumsq = 0.f;
    for (int i = tid; i < DIM; i += 256) {
        float v = row[i];
        sum += v; sumsq += v * v;
    }
    __shared__ float r1[256], r2[256];
    r1[tid] = sum; r2[tid] = sumsq;
    __syncthreads();
    for (int st = 128; st > 0; st >>= 1) {
        if (tid < st) { r1[tid] += r1[tid + st]; r2[tid] += r2[tid + st]; }
        __syncthreads();
    }
    const float mu  = r1[0] * (1.f / DIM);
    const float var = r2[0] * (1.f / DIM) - mu * mu;
    const float rstd = rsqrtf(var + EPS);
    float* orow = out + (size_t)s * DIM;
    for (int i = tid; i < DIM; i += 256)
        orow[i] = (row[i] - mu) * rstd * w[i] + b[i];
}

// ---------------- SGEMM: C[M,N] = A[M,K] @ W[N,K]^T + bias, optional epilogue ----------------
// EPI: 0 = plain store, 1 = tanh-gelu, 2 = + r1[off] + r2[off] (residual fuse)
__device__ __forceinline__ float gelu_tanh(float v) {
    float c = v + 0.044715f * v * v * v;
    return 0.5f * v * (1.f + tanhf(0.7978845608028654f * c));
}

#define BM 128
#define BN 128
#define BKK 8

template<int EPI>
__global__ __launch_bounds__(256)
void sgemm_kernel(const float* __restrict__ A, const float* __restrict__ W,
                  const float* __restrict__ bias, float* __restrict__ C,
                  int M, int N, int K,
                  const float* __restrict__ res1, const float* __restrict__ res2)
{
    __shared__ float As[BKK][BM + 4];
    __shared__ float Ws[BKK][BN + 4];
    const int tid = threadIdx.x;
    const int tx = tid & 15;       // 0..15 -> N
    const int ty = tid >> 4;       // 0..15 -> M
    const int m0 = blockIdx.y * BM;
    const int n0 = blockIdx.x * BN;

    const int lrow = tid >> 1;           // 0..127
    const int lk   = (tid & 1) * 4;      // 0 or 4
    const float* Ag = A + (size_t)(m0 + lrow) * K + lk;
    const float* Wg = W + (size_t)(n0 + lrow) * K + lk;

    float acc[8][8];
    #pragma unroll
    for (int i = 0; i < 8; i++)
        #pragma unroll
        for (int j = 0; j < 8; j++) acc[i][j] = 0.f;

    for (int k0 = 0; k0 < K; k0 += BKK) {
        float4 av = *(const float4*)(Ag + k0);
        float4 wv = *(const float4*)(Wg + k0);
        As[lk + 0][lrow] = av.x; As[lk + 1][lrow] = av.y;
        As[lk + 2][lrow] = av.z; As[lk + 3][lrow] = av.w;
        Ws[lk + 0][lrow] = wv.x; Ws[lk + 1][lrow] = wv.y;
        Ws[lk + 2][lrow] = wv.z; Ws[lk + 3][lrow] = wv.w;
        __syncthreads();
        #pragma unroll
        for (int kk = 0; kk < BKK; kk++) {
            float a[8], b[8];
            *(float4*)(a)     = *(const float4*)&As[kk][ty * 8];
            *(float4*)(a + 4) = *(const float4*)&As[kk][ty * 8 + 4];
            *(float4*)(b)     = *(const float4*)&Ws[kk][tx * 8];
            *(float4*)(b + 4) = *(const float4*)&Ws[kk][tx * 8 + 4];
            #pragma unroll
            for (int i = 0; i < 8; i++)
                #pragma unroll
                for (int j = 0; j < 8; j++)
                    acc[i][j] = fmaf(a[i], b[j], acc[i][j]);
        }
        __syncthreads();
    }

    #pragma unroll
    for (int i = 0; i < 8; i++) {
        const int m = m0 + ty * 8 + i;
        #pragma unroll
        for (int j = 0; j < 8; j++) {
            const int n = n0 + tx * 8 + j;
            float v = acc[i][j] + bias[n];
            if (EPI == 1) v = gelu_tanh(v);
            const size_t off = (size_t)m * N + n;
            if (EPI == 2) v += res1[off] + res2[off];
            C[off] = v;
        }
    }
}

// ---------------- split QKV + RoPE into head-major [H, S, 80] ----------------
__global__ void prep_qkv_kernel(const float* __restrict__ qkv,
                                const int* __restrict__ input_pos)
{
    const int s = blockIdx.x;
    const float pos = (float)input_pos[s];
    const float* row = qkv + (size_t)s * (3 * DIM);
    for (int idx = threadIdx.x; idx < DIM; idx += 256) {
        const int h = idx / HEAD_DIM;
        const int d = idx - h * HEAD_DIM;
        const size_t dsti = ((size_t)h * S_LEN + s) * HEAD_DIM + d;

        float qv = row[idx];
        float kv = row[DIM + idx];
        float vv = row[2 * DIM + idx];

        if (d < ROT_DIM) {
            const int i = (d < 16) ? d : d - 16;
            const float inv = __powf(10000.f, -(float)i / 16.f);
            const float ang = pos * inv;
            const float c = __cosf(ang), sn = __sinf(ang);
            if (d < 16) {
                float q2 = row[idx + 16];
                float k2 = row[DIM + idx + 16];
                qv = qv * c - q2 * sn;
                kv = kv * c - k2 * sn;
            } else {
                float q2 = row[idx - 16];
                float k2 = row[DIM + idx - 16];
                qv = qv * c + q2 * sn;
                kv = kv * c + k2 * sn;
            }
        }
        g_q[dsti] = qv;
        g_k[dsti] = kv;
        g_v[dsti] = vv;
    }
}

// ---------------- flash-style causal attention ----------------
// grid: (S/64 q-blocks, N_HEAD heads), 256 threads.
// Each thread owns query row r = tid&63 and 20 output dims starting at (tid>>6)*20.
#define BQ 64
#define BKV 32

__global__ __launch_bounds__(256)
void attn_kernel(float* __restrict__ y)
{
    __shared__ float sq[BQ][HEAD_DIM + 1];
    __shared__ float skv[BKV][HEAD_DIM + 1];
    __shared__ float ss[BQ][BKV + 1];

    const int qb = blockIdx.x;
    const int h  = blockIdx.y;
    const int tid = threadIdx.x;
    const int r   = tid & 63;
    const int grp = tid >> 6;          // 0..3
    const int j0  = grp * 8;           // score columns owned
    const int d0  = grp * 20;          // output dims owned
    const int qi  = qb * BQ + r;
    const float scale = 0.11180339887498949f;  // 1/sqrt(80)

    // load Q tile
    {
        const float* qg = g_q + ((size_t)h * S_LEN + qb * BQ) * HEAD_DIM;
        for (int i = tid; i < BQ * HEAD_DIM; i += 256)
            sq[i / HEAD_DIM][i % HEAD_DIM] = qg[i];
    }
    __syncthreads();

    float o[20];
    #pragma unroll
    for (int d = 0; d < 20; d++) o[d] = 0.f;
    float m = -INFINITY, l = 0.f;

    const int kb_max = (qb * BQ + BQ - 1) / BKV;   // inclusive
    for (int kb = 0; kb <= kb_max; kb++) {
        // load K tile
        const float* kg = g_k + ((size_t)h * S_LEN + kb * BKV) * HEAD_DIM;
        for (int i = tid; i < BKV * HEAD_DIM; i += 256)
            skv[i / HEAD_DIM][i % HEAD_DIM] = kg[i];
        __syncthreads();

        // scores
        #pragma unroll
        for (int jj = 0; jj < 8; jj++) {
            const int j = j0 + jj;
            const int ki = kb * BKV + j;
            float dot = 0.f;
            #pragma unroll
            for (int dd = 0; dd < HEAD_DIM; dd++)
                dot = fmaf(sq[r][dd], skv[j][dd], dot);
            ss[r][j] = (ki <= qi) ? dot * scale : -1e9f;
        }
        __syncthreads();

        // load V tile (reuse skv)
        const float* vg = g_v + ((size_t)h * S_LEN + kb * BKV) * HEAD_DIM;
        for (int i = tid; i < BKV * HEAD_DIM; i += 256)
            skv[i / HEAD_DIM][i % HEAD_DIM] = vg[i];
        __syncthreads();

        // online softmax update (4 threads per row do identical stats; consistent)
        float mt = -INFINITY;
        #pragma unroll
        for (int j = 0; j < BKV; j++) mt = fmaxf(mt, ss[r][j]);
        const float mnew = fmaxf(m, mt);
        const float alpha = __expf(m - mnew);
        l *= alpha;
        #pragma unroll
        for (int d = 0; d < 20; d++) o[d] *= alpha;
        #pragma unroll
        for (int j = 0; j < BKV; j++) {
            const float p = __expf(ss[r][j] - mnew);
            l += p * 0.25f;   // row sum replicated across 4 threads; scale so l is exact
            #pragma unroll
            for (int d = 0; d < 20; d++)
                o[d] = fmaf(p, skv[j][d0 + d], o[d]);
        }
        m = mnew;
        __syncthreads();
    }

    // l currently holds sum/4 per thread BUT each of the 4 threads accumulated the
    // full row sum scaled by 0.25 identically -> actual row sum = l*4.
    const float inv_l = 1.f / (4.f * l);
    float* yout = y + (size_t)qi * DIM + h * HEAD_DIM + d0;
    #pragma unroll
    for (int d = 0; d < 20; d++) yout[d] = o[d] * inv_l;
}

// ---------------- host launch ----------------
extern "C" void kernel_launch(void* const* d_in, const int* in_sizes, int n_in,
                              void* d_out, int out_size)
{
    const float* x       = (const float*)d_in[0];
    const int*   pos     = (const int*)  d_in[1];
    // d_in[2] = mask (tril, implied by causal loop)
    const float* ln_w    = (const float*)d_in[3];
    const float* ln_b    = (const float*)d_in[4];
    const float* wqkv_w  = (const float*)d_in[5];
    const float* wqkv_b  = (const float*)d_in[6];
    const float* wo_w    = (const float*)d_in[7];
    const float* wo_b    = (const float*)d_in[8];
    const float* w1_w    = (const float*)d_in[9];
    const float* w1_b    = (const float*)d_in[10];
    const float* w2_w    = (const float*)d_in[11];
    const float* w2_b    = (const float*)d_in[12];
    float* out = (float*)d_out;

    float *h_p, *qkv_p, *y_p, *attn_p, *ffn1_p;
    cudaGetSymbolAddress((void**)&h_p,    g_h);
    cudaGetSymbolAddress((void**)&qkv_p,  g_qkv);
    cudaGetSymbolAddress((void**)&y_p,    g_y);
    cudaGetSymbolAddress((void**)&attn_p, g_attn);
    cudaGetSymbolAddress((void**)&ffn1_p, g_ffn1);

    // 1. LayerNorm
    ln_kernel<<<S_LEN, 256>>>(x, ln_w, ln_b, h_p);

    // 2. QKV projection: [2048,2560] @ [7680,2560]^T
    sgemm_kernel<0><<<dim3(3 * DIM / BN, S_LEN / BM), 256>>>(
        h_p, wqkv_w, wqkv_b, qkv_p, S_LEN, 3 * DIM, DIM, nullptr, nullptr);

    // 3. split + RoPE
    prep_qkv_kernel<<<S_LEN, 256>>>(qkv_p, pos);

    // 4. attention
    attn_kernel<<<dim3(S_LEN / BQ, N_HEAD), 256>>>(y_p);

    // 5. output projection
    sgemm_kernel<0><<<dim3(DIM / BN, S_LEN / BM), 256>>>(
        y_p, wo_w, wo_b, attn_p, S_LEN, DIM, DIM, nullptr, nullptr);

    // 6. FFN up + gelu
    sgemm_kernel<1><<<dim3(INTER / BN, S_LEN / BM), 256>>>(
        h_p, w1_w, w1_b, ffn1_p, S_LEN, INTER, DIM, nullptr, nullptr);

    // 7. FFN down + residual fuse: out = ffn2 + attn_out + x
    sgemm_kernel<2><<<dim3(DIM / BN, S_LEN / BM), 256>>>(
        ffn1_p, w2_w, w2_b, out, S_LEN, DIM, INTER, attn_p, x);
}

// round 5
// speedup vs baseline: 2.2705x; 2.2705x over previous
#include <cuda_runtime.h>
#include <cuda_fp16.h>
#include <math.h>
#include <stdint.h>

#define S_LEN 2048
#define DIM 2560
#define N_HEAD 32
#define HEAD_DIM 80
#define ROT_DIM 32
#define INTER 10240
#define EPS 1e-5f

// ---------------- scratch ----------------
__device__ float g_h   [S_LEN * DIM];
__device__ float g_qkv [S_LEN * 3 * DIM];
__device__ float g_q   [N_HEAD * S_LEN * HEAD_DIM];
__device__ float g_k   [N_HEAD * S_LEN * HEAD_DIM];
__device__ float g_v   [N_HEAD * S_LEN * HEAD_DIM];
__device__ float g_y   [S_LEN * DIM];
__device__ float g_attn[S_LEN * DIM];
__device__ float g_ffn1[S_LEN * INTER];

// ---------------- helpers ----------------
__device__ __forceinline__ uint32_t smem_u32(const void* p) {
    uint32_t a;
    asm("{ .reg .u64 t; cvta.to.shared.u64 t, %1; cvt.u32.u64 %0, t; }" : "=r"(a) : "l"(p));
    return a;
}
__device__ __forceinline__ uint32_t pkh(__half a, __half b) {
    __half2 t = __halves2half2(a, b);
    return *(uint32_t*)&t;
}
__device__ __forceinline__ void ldsm4(uint32_t r[4], uint32_t addr) {
    asm volatile("ldmatrix.sync.aligned.m8n8.x4.shared.b16 {%0,%1,%2,%3}, [%4];"
                 : "=r"(r[0]), "=r"(r[1]), "=r"(r[2]), "=r"(r[3]) : "r"(addr));
}
__device__ __forceinline__ void mma16816(float c[4], const uint32_t a[4], const uint32_t b[2]) {
    asm volatile("mma.sync.aligned.m16n8k16.row.col.f32.f16.f16.f32 "
                 "{%0,%1,%2,%3}, {%4,%5,%6,%7}, {%8,%9}, {%0,%1,%2,%3};"
                 : "+f"(c[0]), "+f"(c[1]), "+f"(c[2]), "+f"(c[3])
                 : "r"(a[0]), "r"(a[1]), "r"(a[2]), "r"(a[3]), "r"(b[0]), "r"(b[1]));
}
__device__ __forceinline__ float gelu_tanh(float v) {
    float c = v + 0.044715f * v * v * v;
    return 0.5f * v * (1.f + tanhf(0.7978845608028654f * c));
}

// ---------------- mma.sync fp16x3 GEMM: C[M,N] = A[M,K] @ W[N,K]^T + bias ----------------
// tiles: BM=128, BN=128, BK=32. smem rows padded to 40 halves (80B stride).
#define BK 32
#define LDT 40
#define TILE_H (128 * LDT)          // halves per tile
#define TILE_B (TILE_H * 2)         // bytes per tile (10240)
#define BUF_H  (4 * TILE_H)         // Ah | Al | Wh | Wl
#define SMEM_DYN (2 * BUF_H * 2)    // 81920 bytes

// EPI: 0 plain, 1 gelu, 2 +res1+res2
template<int EPI>
__global__ __launch_bounds__(256)
void mma_gemm(const float* __restrict__ A, const float* __restrict__ W,
              const float* __restrict__ bias, float* __restrict__ C,
              int M, int N, int K,
              const float* __restrict__ res1, const float* __restrict__ res2)
{
    extern __shared__ __align__(16) __half smem[];
    const int tid  = threadIdx.x;
    const int lane = tid & 31;
    const int wid  = tid >> 5;
    const int wm   = (wid & 3) * 32;       // warp m offset in tile
    const int wn   = (wid >> 2) * 64;      // warp n offset in tile
    const int m0 = blockIdx.x * 128;
    const int n0 = blockIdx.y * 128;

    float acc[2][8][4];
    #pragma unroll
    for (int i = 0; i < 2; i++)
        #pragma unroll
        for (int j = 0; j < 8; j++)
            #pragma unroll
            for (int q = 0; q < 4; q++) acc[i][j][q] = 0.f;

    const int nch = K / BK;

    float4 ra[4], rw[4];

    // ---- stage chunk k0 into registers ----
    auto stage = [&](int k0) {
        #pragma unroll
        for (int r = 0; r < 4; r++) {
            const int idx = r * 256 + tid;
            const int rr = idx >> 3;
            const int c4 = idx & 7;
            ra[r] = *(const float4*)(A + (size_t)(m0 + rr) * K + (k0 + c4 * 4));
            rw[r] = *(const float4*)(W + (size_t)(n0 + rr) * K + (k0 + c4 * 4));
        }
    };
    // ---- convert + store registers into smem buffer b ----
    auto storebuf = [&](int b) {
        __half* buf = smem + b * BUF_H;
        #pragma unroll
        for (int r = 0; r < 4; r++) {
            const int idx = r * 256 + tid;
            const int rr = idx >> 3;
            const int c4 = idx & 7;
            const int off = rr * LDT + c4 * 4;
            float4 v = ra[r];
            __half h0 = __float2half_rn(v.x), h1 = __float2half_rn(v.y);
            __half h2 = __float2half_rn(v.z), h3 = __float2half_rn(v.w);
            __half l0 = __float2half_rn(v.x - __half2float(h0));
            __half l1 = __float2half_rn(v.y - __half2float(h1));
            __half l2 = __float2half_rn(v.z - __half2float(h2));
            __half l3 = __float2half_rn(v.w - __half2float(h3));
            *(uint2*)(buf + off)          = make_uint2(pkh(h0, h1), pkh(h2, h3));
            *(uint2*)(buf + TILE_H + off) = make_uint2(pkh(l0, l1), pkh(l2, l3));
            v = rw[r];
            h0 = __float2half_rn(v.x); h1 = __float2half_rn(v.y);
            h2 = __float2half_rn(v.z); h3 = __float2half_rn(v.w);
            l0 = __float2half_rn(v.x - __half2float(h0));
            l1 = __float2half_rn(v.y - __half2float(h1));
            l2 = __float2half_rn(v.z - __half2float(h2));
            l3 = __float2half_rn(v.w - __half2float(h3));
            *(uint2*)(buf + 2 * TILE_H + off) = make_uint2(pkh(h0, h1), pkh(h2, h3));
            *(uint2*)(buf + 3 * TILE_H + off) = make_uint2(pkh(l0, l1), pkh(l2, l3));
        }
    };

    // ldmatrix lane address components (non-trans for both operands)
    const int a_row = wm + (lane & 15);
    const int a_colsel = (lane >> 4) << 3;                    // 0 or 8
    const int b_rowsel = ((lane >> 4) & 1) * 8 + (lane & 7);  // row within 16-n pair
    const int b_colsel = ((lane >> 3) & 1) * 8;               // 0 or 8

    auto compute = [&](int b) {
        const uint32_t base = smem_u32(smem + b * BUF_H);
        #pragma unroll
        for (int ks = 0; ks < 2; ks++) {
            const int kb = ks * 16;
            uint32_t ah[2][4], al[2][4], bh[8][2], bl[8][2];
            #pragma unroll
            for (int i = 0; i < 2; i++) {
                const uint32_t off = ((a_row + i * 16) * LDT + kb + a_colsel) * 2;
                ldsm4(ah[i], base + off);
                ldsm4(al[i], base + TILE_B + off);
            }
            #pragma unroll
            for (int p = 0; p < 4; p++) {
                const int nrow = wn + p * 16 + b_rowsel;
                const uint32_t off = (nrow * LDT + kb + b_colsel) * 2;
                uint32_t t[4];
                ldsm4(t, base + 2 * TILE_B + off);
                bh[2 * p][0] = t[0]; bh[2 * p][1] = t[1];
                bh[2 * p + 1][0] = t[2]; bh[2 * p + 1][1] = t[3];
                ldsm4(t, base + 3 * TILE_B + off);
                bl[2 * p][0] = t[0]; bl[2 * p][1] = t[1];
                bl[2 * p + 1][0] = t[2]; bl[2 * p + 1][1] = t[3];
            }
            #pragma unroll
            for (int i = 0; i < 2; i++)
                #pragma unroll
                for (int j = 0; j < 8; j++) mma16816(acc[i][j], ah[i], bh[j]);
            #pragma unroll
            for (int i = 0; i < 2; i++)
                #pragma unroll
                for (int j = 0; j < 8; j++) mma16816(acc[i][j], ah[i], bl[j]);
            #pragma unroll
            for (int i = 0; i < 2; i++)
                #pragma unroll
                for (int j = 0; j < 8; j++) mma16816(acc[i][j], al[i], bh[j]);
        }
    };

    stage(0);
    storebuf(0);
    __syncthreads();

    for (int ch = 0; ch < nch; ch++) {
        if (ch + 1 < nch) stage((ch + 1) * BK);
        compute(ch & 1);
        __syncthreads();
        if (ch + 1 < nch) storebuf((ch + 1) & 1);
        __syncthreads();
    }

    // ---- epilogue ----
    #pragma unroll
    for (int i = 0; i < 2; i++) {
        const int row = m0 + wm + i * 16 + (lane >> 2);
        #pragma unroll
        for (int j = 0; j < 8; j++) {
            const int col = n0 + wn + j * 8 + (lane & 3) * 2;
            const float b0 = bias[col], b1 = bias[col + 1];
            #pragma unroll
            for (int half_ = 0; half_ < 2; half_++) {
                const int r = row + half_ * 8;
                float v0 = acc[i][j][half_ * 2 + 0] + b0;
                float v1 = acc[i][j][half_ * 2 + 1] + b1;
                if (EPI == 1) { v0 = gelu_tanh(v0); v1 = gelu_tanh(v1); }
                const size_t off = (size_t)r * N + col;
                if (EPI == 2) {
                    float2 r1 = *(const float2*)(res1 + off);
                    float2 r2 = *(const float2*)(res2 + off);
                    v0 += r1.x + r2.x; v1 += r1.y + r2.y;
                }
                *(float2*)(C + off) = make_float2(v0, v1);
            }
        }
    }
}

// ---------------- LayerNorm ----------------
__global__ void ln_kernel(const float* __restrict__ x,
                          const float* __restrict__ w,
                          const float* __restrict__ b,
                          float* __restrict__ out)
{
    const int s = blockIdx.x;
    const int tid = threadIdx.x;
    const float* row = x + (size_t)s * DIM;
    float sum = 0.f, sumsq = 0.f;
    for (int i = tid; i < DIM; i += 256) {
        float v = row[i];
        sum += v; sumsq += v * v;
    }
    __shared__ float r1[256], r2[256];
    r1[tid] = sum; r2[tid] = sumsq;
    __syncthreads();
    for (int st = 128; st > 0; st >>= 1) {
        if (tid < st) { r1[tid] += r1[tid + st]; r2[tid] += r2[tid + st]; }
        __syncthreads();
    }
    const float mu  = r1[0] * (1.f / DIM);
    const float var = r2[0] * (1.f / DIM) - mu * mu;
    const float rstd = rsqrtf(var + EPS);
    float* orow = out + (size_t)s * DIM;
    for (int i = tid; i < DIM; i += 256)
        orow[i] = (row[i] - mu) * rstd * w[i] + b[i];
}

// ---------------- split QKV + RoPE ----------------
__global__ void prep_qkv_kernel(const float* __restrict__ qkv,
                                const int* __restrict__ input_pos)
{
    const int s = blockIdx.x;
    const float pos = (float)input_pos[s];
    const float* row = qkv + (size_t)s * (3 * DIM);
    for (int idx = threadIdx.x; idx < DIM; idx += 256) {
        const int h = idx / HEAD_DIM;
        const int d = idx - h * HEAD_DIM;
        const size_t dsti = ((size_t)h * S_LEN + s) * HEAD_DIM + d;

        float qv = row[idx];
        float kv = row[DIM + idx];
        float vv = row[2 * DIM + idx];

        if (d < ROT_DIM) {
            const int i = (d < 16) ? d : d - 16;
            const float inv = __powf(10000.f, -(float)i / 16.f);
            const float ang = pos * inv;
            const float c = __cosf(ang), sn = __sinf(ang);
            if (d < 16) {
                float q2 = row[idx + 16];
                float k2 = row[DIM + idx + 16];
                qv = qv * c - q2 * sn;
                kv = kv * c - k2 * sn;
            } else {
                float q2 = row[idx - 16];
                float k2 = row[DIM + idx - 16];
                qv = qv * c + q2 * sn;
                kv = kv * c + k2 * sn;
            }
        }
        g_q[dsti] = qv;
        g_k[dsti] = kv;
        g_v[dsti] = vv;
    }
}

// ---------------- flash-style causal attention ----------------
#define BQ 64
#define BKV 32

__global__ __launch_bounds__(256)
void attn_kernel(float* __restrict__ y)
{
    __shared__ float sq[BQ][HEAD_DIM + 1];
    __shared__ float skv[BKV][HEAD_DIM + 1];
    __shared__ float ss[BQ][BKV + 1];

    const int qb = blockIdx.x;
    const int h  = blockIdx.y;
    const int tid = threadIdx.x;
    const int r   = tid & 63;
    const int grp = tid >> 6;
    const int j0  = grp * 8;
    const int d0  = grp * 20;
    const int qi  = qb * BQ + r;
    const float scale = 0.11180339887498949f;

    {
        const float* qg = g_q + ((size_t)h * S_LEN + qb * BQ) * HEAD_DIM;
        for (int i = tid; i < BQ * HEAD_DIM; i += 256)
            sq[i / HEAD_DIM][i % HEAD_DIM] = qg[i];
    }
    __syncthreads();

    float o[20];
    #pragma unroll
    for (int d = 0; d < 20; d++) o[d] = 0.f;
    float m = -INFINITY, l = 0.f;

    const int kb_max = (qb * BQ + BQ - 1) / BKV;
    for (int kb = 0; kb <= kb_max; kb++) {
        const float* kg = g_k + ((size_t)h * S_LEN + kb * BKV) * HEAD_DIM;
        for (int i = tid; i < BKV * HEAD_DIM; i += 256)
            skv[i / HEAD_DIM][i % HEAD_DIM] = kg[i];
        __syncthreads();

        #pragma unroll
        for (int jj = 0; jj < 8; jj++) {
            const int j = j0 + jj;
            const int ki = kb * BKV + j;
            float dot = 0.f;
            #pragma unroll
            for (int dd = 0; dd < HEAD_DIM; dd++)
                dot = fmaf(sq[r][dd], skv[j][dd], dot);
            ss[r][j] = (ki <= qi) ? dot * scale : -1e9f;
        }
        __syncthreads();

        const float* vg = g_v + ((size_t)h * S_LEN + kb * BKV) * HEAD_DIM;
        for (int i = tid; i < BKV * HEAD_DIM; i += 256)
            skv[i / HEAD_DIM][i % HEAD_DIM] = vg[i];
        __syncthreads();

        float mt = -INFINITY;
        #pragma unroll
        for (int j = 0; j < BKV; j++) mt = fmaxf(mt, ss[r][j]);
        const float mnew = fmaxf(m, mt);
        const float alpha = __expf(m - mnew);
        l *= alpha;
        #pragma unroll
        for (int d = 0; d < 20; d++) o[d] *= alpha;
        #pragma unroll
        for (int j = 0; j < BKV; j++) {
            const float p = __expf(ss[r][j] - mnew);
            l += p * 0.25f;
            #pragma unroll
            for (int d = 0; d < 20; d++)
                o[d] = fmaf(p, skv[j][d0 + d], o[d]);
        }
        m = mnew;
        __syncthreads();
    }

    const float inv_l = 1.f / (4.f * l);
    float* yout = y + (size_t)qi * DIM + h * HEAD_DIM + d0;
    #pragma unroll
    for (int d = 0; d < 20; d++) yout[d] = o[d] * inv_l;
}

// ---------------- host launch ----------------
extern "C" void kernel_launch(void* const* d_in, const int* in_sizes, int n_in,
                              void* d_out, int out_size)
{
    const float* x       = (const float*)d_in[0];
    const int*   pos     = (const int*)  d_in[1];
    const float* ln_w    = (const float*)d_in[3];
    const float* ln_b    = (const float*)d_in[4];
    const float* wqkv_w  = (const float*)d_in[5];
    const float* wqkv_b  = (const float*)d_in[6];
    const float* wo_w    = (const float*)d_in[7];
    const float* wo_b    = (const float*)d_in[8];
    const float* w1_w    = (const float*)d_in[9];
    const float* w1_b    = (const float*)d_in[10];
    const float* w2_w    = (const float*)d_in[11];
    const float* w2_b    = (const float*)d_in[12];
    float* out = (float*)d_out;

    float *h_p, *qkv_p, *y_p, *attn_p, *ffn1_p;
    cudaGetSymbolAddress((void**)&h_p,    g_h);
    cudaGetSymbolAddress((void**)&qkv_p,  g_qkv);
    cudaGetSymbolAddress((void**)&y_p,    g_y);
    cudaGetSymbolAddress((void**)&attn_p, g_attn);
    cudaGetSymbolAddress((void**)&ffn1_p, g_ffn1);

    cudaFuncSetAttribute(mma_gemm<0>, cudaFuncAttributeMaxDynamicSharedMemorySize, SMEM_DYN);
    cudaFuncSetAttribute(mma_gemm<1>, cudaFuncAttributeMaxDynamicSharedMemorySize, SMEM_DYN);
    cudaFuncSetAttribute(mma_gemm<2>, cudaFuncAttributeMaxDynamicSharedMemorySize, SMEM_DYN);

    // 1. LayerNorm
    ln_kernel<<<S_LEN, 256>>>(x, ln_w, ln_b, h_p);

    // 2. QKV projection: [2048,2560] @ [7680,2560]^T
    mma_gemm<0><<<dim3(S_LEN / 128, 3 * DIM / 128), 256, SMEM_DYN>>>(
        h_p, wqkv_w, wqkv_b, qkv_p, S_LEN, 3 * DIM, DIM, nullptr, nullptr);

    // 3. split + RoPE
    prep_qkv_kernel<<<S_LEN, 256>>>(qkv_p, pos);

    // 4. attention
    attn_kernel<<<dim3(S_LEN / BQ, N_HEAD), 256>>>(y_p);

    // 5. output projection
    mma_gemm<0><<<dim3(S_LEN / 128, DIM / 128), 256, SMEM_DYN>>>(
        y_p, wo_w, wo_b, attn_p, S_LEN, DIM, DIM, nullptr, nullptr);

    // 6. FFN up + gelu
    mma_gemm<1><<<dim3(S_LEN / 128, INTER / 128), 256, SMEM_DYN>>>(
        h_p, w1_w, w1_b, ffn1_p, S_LEN, INTER, DIM, nullptr, nullptr);

    // 7. FFN down + residual fuse
    mma_gemm<2><<<dim3(S_LEN / 128, DIM / 128), 256, SMEM_DYN>>>(
        ffn1_p, w2_w, w2_b, out, S_LEN, DIM, INTER, attn_p, x);
}